// round 12
// baseline (speedup 1.0000x reference)
#include <cuda_runtime.h>
#include <cuda_bf16.h>
#include <cstdint>

// Problem constants
#define B_WIN   4096
#define SEQ     64
#define CDIM    256
#define NHEAD   8
#define HDIM    32
#define NWIN    64
#define MAX_LOGIT 4.6051701859880913680f  // log(100)
#define MTOT    (B_WIN * SEQ)             // 262144

// ---------------- scratch (device globals; no runtime allocation) ----------
__device__ __align__(16) float g_qkv[(size_t)MTOT * 3 * CDIM];
__device__ __align__(16) __nv_bfloat16 g_xh[(size_t)MTOT * CDIM];
__device__ __align__(16) __nv_bfloat16 g_xl[(size_t)MTOT * CDIM];
__device__ __align__(16) __nv_bfloat16 g_ah[(size_t)MTOT * CDIM];
__device__ __align__(16) __nv_bfloat16 g_al[(size_t)MTOT * CDIM];
__device__ __align__(16) __nv_bfloat16 g_wqh[3 * CDIM * CDIM];
__device__ __align__(16) __nv_bfloat16 g_wql[3 * CDIM * CDIM];
__device__ __align__(16) __nv_bfloat16 g_wph[CDIM * CDIM];
__device__ __align__(16) __nv_bfloat16 g_wpl[CDIM * CDIM];

// ================= common helpers ==========================================
__device__ __forceinline__ uint32_t pack_bf2(float a, float b) {
    __nv_bfloat162 t = __floats2bfloat162_rn(a, b);
    return *reinterpret_cast<uint32_t*>(&t);
}

__device__ __forceinline__ void ldsm_x4(uint32_t addr, uint32_t& r0, uint32_t& r1,
                                        uint32_t& r2, uint32_t& r3) {
    asm volatile("ldmatrix.sync.aligned.m8n8.x4.shared.b16 {%0,%1,%2,%3}, [%4];"
                 : "=r"(r0), "=r"(r1), "=r"(r2), "=r"(r3) : "r"(addr));
}

__device__ __forceinline__ void mma_bf16(float* c, const uint32_t* a,
                                         uint32_t b0, uint32_t b1) {
    asm volatile(
        "mma.sync.aligned.m16n8k16.row.col.f32.bf16.bf16.f32 "
        "{%0,%1,%2,%3}, {%4,%5,%6,%7}, {%8,%9}, {%0,%1,%2,%3};"
        : "+f"(c[0]), "+f"(c[1]), "+f"(c[2]), "+f"(c[3])
        : "r"(a[0]), "r"(a[1]), "r"(a[2]), "r"(a[3]), "r"(b0), "r"(b1));
}

__device__ __forceinline__ void split4(float4 v, uint2& hi, uint2& lo) {
    float vv[4] = {v.x, v.y, v.z, v.w};
    float hf[4], lf[4];
    #pragma unroll
    for (int j = 0; j < 4; j++) {
        __nv_bfloat16 h = __float2bfloat16_rn(vv[j]);
        hf[j] = __bfloat162float(h);
        lf[j] = vv[j] - hf[j];
    }
    hi.x = pack_bf2(hf[0], hf[1]); hi.y = pack_bf2(hf[2], hf[3]);
    lo.x = pack_bf2(lf[0], lf[1]); lo.y = pack_bf2(lf[2], lf[3]);
}

// ================= split kernel: fp32 -> bf16 hi/lo ========================
__global__ __launch_bounds__(256) void split_kernel(
    const float4* __restrict__ in, uint2* __restrict__ hi,
    uint2* __restrict__ lo, int n4)
{
    int i = blockIdx.x * 256 + threadIdx.x;
    if (i >= n4) return;
    uint2 h, l;
    split4(in[i], h, l);
    hi[i] = h; lo[i] = l;
}

// ================= preconverted bf16 GEMM ==================================
// C[M x N] = (Ah+Al)[M x K] * (Bh+Bl)[N x K]^T + bias[N], 3-pass bf16 split.
// Register prefetch of next k-block; double-buffered smem; ONE sync per kb.
#define GBM 128
#define GBN 64
#define GBK 32
#define LDS 40
// stage layout (bytes): Ah @0 (10240), Al @10240, Bh @20480 (5120), Bl @25600
#define STG_BYTES 30720
#define OFF_AH 0
#define OFF_AL 10240
#define OFF_BH 20480
#define OFF_BL 25600

__global__ __launch_bounds__(256, 2) void gemm_pre(
    const __nv_bfloat16* __restrict__ Ah, const __nv_bfloat16* __restrict__ Al,
    const __nv_bfloat16* __restrict__ Bh, const __nv_bfloat16* __restrict__ Bl,
    const float* __restrict__ bias, float* __restrict__ C,
    int M, int N, int K)
{
    extern __shared__ unsigned char smraw[];
    const uint32_t smBase = (uint32_t)__cvta_generic_to_shared(smraw);

    const int tid  = threadIdx.x;
    const int lane = tid & 31;
    const int wid  = tid >> 5;
    const int bm   = blockIdx.y * GBM;
    const int bn   = blockIdx.x * GBN;
    const int wm   = (wid & 3) * 32;
    const int wn   = (wid >> 2) * 32;

    // ---- ldmatrix fragment addressing ----
    const int lr   = lane & 7;
    const int seg  = lane >> 3;
    const int frow = lr + (seg & 1) * 8;
    const int fcol = (seg >> 1) * 8;

    uint32_t oAh[2], oAl[2], oBh[2], oBl[2];
    #pragma unroll
    for (int mt = 0; mt < 2; mt++) {
        uint32_t off = ((wm + mt * 16 + frow) * LDS + fcol) * 2;
        oAh[mt] = off + OFF_AH;
        oAl[mt] = off + OFF_AL;
    }
    #pragma unroll
    for (int p = 0; p < 2; p++) {
        uint32_t off = ((wn + p * 16 + frow) * LDS + fcol) * 2;
        oBh[p] = off + OFF_BH;
        oBl[p] = off + OFF_BL;
    }

    float acc[2][4][4];
    #pragma unroll
    for (int mt = 0; mt < 2; mt++)
        #pragma unroll
        for (int nt = 0; nt < 4; nt++)
            #pragma unroll
            for (int j = 0; j < 4; j++) acc[mt][nt][j] = 0.f;

    // ---- per-thread load slots (uint2 = 4 bf16) ----
    // A: 128x32 hi+lo -> 4 uint2 each; B: 64x32 -> 2 each.
    uint2 pah[4], pal[4], pbh[2], pbl[2];

    auto ldg_stage = [&](int kb) {
        const int ke = kb * GBK;
        #pragma unroll
        for (int i = 0; i < 4; i++) {
            int s = i * 256 + tid;
            int r = s >> 3, c = s & 7;
            size_t go = (size_t)(bm + r) * K + ke + c * 4;
            pah[i] = *reinterpret_cast<const uint2*>(Ah + go);
            pal[i] = *reinterpret_cast<const uint2*>(Al + go);
        }
        #pragma unroll
        for (int i = 0; i < 2; i++) {
            int s = i * 256 + tid;
            int r = s >> 3, c = s & 7;
            size_t go = (size_t)(bn + r) * K + ke + c * 4;
            pbh[i] = *reinterpret_cast<const uint2*>(Bh + go);
            pbl[i] = *reinterpret_cast<const uint2*>(Bl + go);
        }
    };
    auto sts_stage = [&](int buf) {
        unsigned char* sb = smraw + buf * STG_BYTES;
        #pragma unroll
        for (int i = 0; i < 4; i++) {
            int s = i * 256 + tid;
            int r = s >> 3, c = s & 7;
            *reinterpret_cast<uint2*>(sb + OFF_AH + r * 80 + c * 8) = pah[i];
            *reinterpret_cast<uint2*>(sb + OFF_AL + r * 80 + c * 8) = pal[i];
        }
        #pragma unroll
        for (int i = 0; i < 2; i++) {
            int s = i * 256 + tid;
            int r = s >> 3, c = s & 7;
            *reinterpret_cast<uint2*>(sb + OFF_BH + r * 80 + c * 8) = pbh[i];
            *reinterpret_cast<uint2*>(sb + OFF_BL + r * 80 + c * 8) = pbl[i];
        }
    };

    const int nkb = K / GBK;   // 8

    ldg_stage(0);
    sts_stage(0);
    __syncthreads();

    for (int kb = 0; kb < nkb; kb++) {
        if (kb + 1 < nkb) ldg_stage(kb + 1);   // overlap with compute

        const uint32_t so = smBase + (uint32_t)(kb & 1) * STG_BYTES;
        #pragma unroll
        for (int ks = 0; ks < 2; ks++) {
            const uint32_t koff = ks * 32;
            uint32_t ah[2][4], al[2][4], bh[2][4], bl[2][4];
            #pragma unroll
            for (int mt = 0; mt < 2; mt++) {
                ldsm_x4(so + oAh[mt] + koff, ah[mt][0], ah[mt][1], ah[mt][2], ah[mt][3]);
                ldsm_x4(so + oAl[mt] + koff, al[mt][0], al[mt][1], al[mt][2], al[mt][3]);
            }
            #pragma unroll
            for (int p = 0; p < 2; p++) {
                ldsm_x4(so + oBh[p] + koff, bh[p][0], bh[p][1], bh[p][2], bh[p][3]);
                ldsm_x4(so + oBl[p] + koff, bl[p][0], bl[p][1], bl[p][2], bl[p][3]);
            }
            #pragma unroll
            for (int mt = 0; mt < 2; mt++) {
                #pragma unroll
                for (int nt = 0; nt < 4; nt++) {
                    int p = nt >> 1, q = nt & 1;
                    uint32_t b0h = bh[p][q], b1h = bh[p][q + 2];
                    uint32_t b0l = bl[p][q], b1l = bl[p][q + 2];
                    mma_bf16(acc[mt][nt], ah[mt], b0h, b1h);
                    mma_bf16(acc[mt][nt], ah[mt], b0l, b1l);
                    mma_bf16(acc[mt][nt], al[mt], b0h, b1h);
                }
            }
        }

        if (kb + 1 < nkb) {
            sts_stage((kb + 1) & 1);   // writes the buffer nobody reads
            __syncthreads();           // single barrier per k-block
        }
    }

    // ---- epilogue: bias + store ----
    const int er = lane >> 2;
    const int ec = (lane & 3) * 2;
    #pragma unroll
    for (int mt = 0; mt < 2; mt++) {
        #pragma unroll
        for (int nt = 0; nt < 4; nt++) {
            int row = bm + wm + mt * 16 + er;
            int col = bn + wn + nt * 8 + ec;
            float b0 = bias[col], b1 = bias[col + 1];
            float2 o0 = make_float2(acc[mt][nt][0] + b0, acc[mt][nt][1] + b1);
            float2 o1 = make_float2(acc[mt][nt][2] + b0, acc[mt][nt][3] + b1);
            *reinterpret_cast<float2*>(C + (size_t)row * N + col) = o0;
            *reinterpret_cast<float2*>(C + (size_t)(row + 8) * N + col) = o1;
        }
    }
}

// ============ fused RoPE + norm + tensor-core attention per (b,h) ==========
#define VLD 72   // V^T row length (64 + 8 pad)

__global__ __launch_bounds__(128) void attn_mma_kernel(
    const float* __restrict__ mask, const float* __restrict__ logit_scale,
    __nv_bfloat16* __restrict__ oh, __nv_bfloat16* __restrict__ ol)
{
    const int h = blockIdx.x;
    const int b = blockIdx.y;
    const int w = b & (NWIN - 1);
    const int tid  = threadIdx.x;
    const int lane = tid & 31;
    const int wid  = tid >> 5;

    __shared__ __align__(16) __nv_bfloat16 qh[SEQ * LDS];
    __shared__ __align__(16) __nv_bfloat16 ql[SEQ * LDS];
    __shared__ __align__(16) __nv_bfloat16 kh[SEQ * LDS];
    __shared__ __align__(16) __nv_bfloat16 kl[SEQ * LDS];
    __shared__ __align__(16) __nv_bfloat16 vth[HDIM * VLD];
    __shared__ __align__(16) __nv_bfloat16 vtl[HDIM * VLD];
    __shared__ float msk[SEQ][SEQ + 4];

    const float* base = g_qkv + (size_t)b * SEQ * (3 * CDIM) + h * HDIM;

    // ---- load q or k row, RoPE + normalize, split to bf16 hi/lo ----
    {
        const int s = tid >> 6;
        const int n = tid & 63;
        const float* rp = base + (size_t)n * (3 * CDIM) + s * CDIM;
        float v[32];
        #pragma unroll
        for (int i = 0; i < 8; i++) {
            float4 t = *reinterpret_cast<const float4*>(rp + i * 4);
            v[i*4+0]=t.x; v[i*4+1]=t.y; v[i*4+2]=t.z; v[i*4+3]=t.w;
        }
        float r[32];
        const float tp = (float)n + 0.1f;
        #pragma unroll
        for (int i = 0; i < 16; i++) {
            float inv_freq = exp2f(-(float)i * 0.8304820237218405f);
            float ang = tp * inv_freq;
            float sn = sinf(ang), cs = cosf(ang);
            r[i]      = v[i] * cs - v[i + 16] * sn;
            r[i + 16] = v[i] * sn + v[i + 16] * cs;
        }
        float ss = 0.f;
        #pragma unroll
        for (int i = 0; i < 32; i++) ss += r[i] * r[i];
        float inv = 1.0f / fmaxf(sqrtf(ss), 1e-12f);
        __nv_bfloat16* dh = (s == 0 ? qh : kh) + n * LDS;
        __nv_bfloat16* dl = (s == 0 ? ql : kl) + n * LDS;
        #pragma unroll
        for (int i = 0; i < 32; i += 2) {
            float a0 = r[i] * inv, a1 = r[i + 1] * inv;
            __nv_bfloat162 hi2 = __floats2bfloat162_rn(a0, a1);
            float h0 = __bfloat162float(__low2bfloat16(hi2));
            float h1 = __bfloat162float(__high2bfloat16(hi2));
            *reinterpret_cast<uint32_t*>(dh + i) = *reinterpret_cast<uint32_t*>(&hi2);
            *reinterpret_cast<uint32_t*>(dl + i) = pack_bf2(a0 - h0, a1 - h1);
        }
    }
    // ---- load V transposed, split hi/lo ----
    {
        const int n = tid & 63;
        const int dh0 = (tid >> 6) * 16;
        const float* rp = base + (size_t)n * (3 * CDIM) + 2 * CDIM + dh0;
        #pragma unroll
        for (int i = 0; i < 4; i++) {
            float4 t = *reinterpret_cast<const float4*>(rp + i * 4);
            float vv[4] = {t.x, t.y, t.z, t.w};
            #pragma unroll
            for (int j = 0; j < 4; j++) {
                int d = dh0 + i * 4 + j;
                __nv_bfloat16 hb = __float2bfloat16_rn(vv[j]);
                vth[d * VLD + n] = hb;
                vtl[d * VLD + n] = __float2bfloat16_rn(vv[j] - __bfloat162float(hb));
            }
        }
    }
    // ---- load mask tile ----
    {
        const float* mp = mask + (size_t)w * SEQ * SEQ;
        #pragma unroll
        for (int i = 0; i < 8; i++) {
            int s = i * 128 + tid;
            int r = s >> 4, c4 = (s & 15) * 4;
            *reinterpret_cast<float4*>(&msk[r][c4]) =
                *reinterpret_cast<const float4*>(mp + r * SEQ + c4);
        }
    }
    const float scale = expf(fminf(logit_scale[h], MAX_LOGIT));
    __syncthreads();

    const int lr   = lane & 7;
    const int seg  = lane >> 3;
    const int frow = lr + (seg & 1) * 8;
    const int fcol = (seg >> 1) * 8;
    const int wm   = wid * 16;

    const uint32_t bQh = (uint32_t)__cvta_generic_to_shared(qh);
    const uint32_t bQl = (uint32_t)__cvta_generic_to_shared(ql);
    const uint32_t bKh = (uint32_t)__cvta_generic_to_shared(kh);
    const uint32_t bKl = (uint32_t)__cvta_generic_to_shared(kl);
    const uint32_t bVh = (uint32_t)__cvta_generic_to_shared(vth);
    const uint32_t bVl = (uint32_t)__cvta_generic_to_shared(vtl);

    const uint32_t aQ = ((wm + frow) * LDS + fcol) * 2;

    // ---- S = qn . kn^T (3-pass split) ----
    float acc[8][4];
    #pragma unroll
    for (int j = 0; j < 8; j++)
        #pragma unroll
        for (int u = 0; u < 4; u++) acc[j][u] = 0.f;

    #pragma unroll
    for (int ks = 0; ks < 2; ks++) {
        const uint32_t koff = ks * 32;
        uint32_t ah[4], al[4];
        ldsm_x4(bQh + aQ + koff, ah[0], ah[1], ah[2], ah[3]);
        ldsm_x4(bQl + aQ + koff, al[0], al[1], al[2], al[3]);
        uint32_t bhf[4][4], blf[4][4];
        #pragma unroll
        for (int p = 0; p < 4; p++) {
            uint32_t off = ((p * 16 + frow) * LDS + fcol) * 2 + koff;
            ldsm_x4(bKh + off, bhf[p][0], bhf[p][1], bhf[p][2], bhf[p][3]);
            ldsm_x4(bKl + off, blf[p][0], blf[p][1], blf[p][2], blf[p][3]);
        }
        #pragma unroll
        for (int j = 0; j < 8; j++) {
            int p = j >> 1, q = j & 1;
            mma_bf16(acc[j], ah, bhf[p][q], bhf[p][q + 2]);
            mma_bf16(acc[j], ah, blf[p][q], blf[p][q + 2]);
            mma_bf16(acc[j], al, bhf[p][q], bhf[p][q + 2]);
        }
    }

    // ---- scale + mask + softmax in registers ----
    {
        const int r0 = wm + (lane >> 2);
        const int c0 = (lane & 3) * 2;
        float m0 = -1e30f, m1 = -1e30f;
        #pragma unroll
        for (int j = 0; j < 8; j++) {
            acc[j][0] = fmaf(acc[j][0], scale, msk[r0][8*j + c0]);
            acc[j][1] = fmaf(acc[j][1], scale, msk[r0][8*j + c0 + 1]);
            acc[j][2] = fmaf(acc[j][2], scale, msk[r0 + 8][8*j + c0]);
            acc[j][3] = fmaf(acc[j][3], scale, msk[r0 + 8][8*j + c0 + 1]);
            m0 = fmaxf(m0, fmaxf(acc[j][0], acc[j][1]));
            m1 = fmaxf(m1, fmaxf(acc[j][2], acc[j][3]));
        }
        m0 = fmaxf(m0, __shfl_xor_sync(0xffffffffu, m0, 1));
        m0 = fmaxf(m0, __shfl_xor_sync(0xffffffffu, m0, 2));
        m1 = fmaxf(m1, __shfl_xor_sync(0xffffffffu, m1, 1));
        m1 = fmaxf(m1, __shfl_xor_sync(0xffffffffu, m1, 2));
        float s0 = 0.f, s1 = 0.f;
        #pragma unroll
        for (int j = 0; j < 8; j++) {
            acc[j][0] = __expf(acc[j][0] - m0);
            acc[j][1] = __expf(acc[j][1] - m0);
            acc[j][2] = __expf(acc[j][2] - m1);
            acc[j][3] = __expf(acc[j][3] - m1);
            s0 += acc[j][0] + acc[j][1];
            s1 += acc[j][2] + acc[j][3];
        }
        s0 += __shfl_xor_sync(0xffffffffu, s0, 1);
        s0 += __shfl_xor_sync(0xffffffffu, s0, 2);
        s1 += __shfl_xor_sync(0xffffffffu, s1, 1);
        s1 += __shfl_xor_sync(0xffffffffu, s1, 2);
        float i0 = 1.0f / s0, i1 = 1.0f / s1;
        #pragma unroll
        for (int j = 0; j < 8; j++) {
            acc[j][0] *= i0; acc[j][1] *= i0;
            acc[j][2] *= i1; acc[j][3] *= i1;
        }
    }

    // ---- out = P . V ----
    float acco[4][4];
    #pragma unroll
    for (int j = 0; j < 4; j++)
        #pragma unroll
        for (int u = 0; u < 4; u++) acco[j][u] = 0.f;

    #pragma unroll
    for (int ks = 0; ks < 4; ks++) {
        uint32_t pah[4], pal[4];
        {
            const float* t0 = acc[2 * ks];
            const float* t1 = acc[2 * ks + 1];
            float hh;
            __nv_bfloat162 x;
            x = __floats2bfloat162_rn(t0[0], t0[1]);
            pah[0] = *reinterpret_cast<uint32_t*>(&x);
            hh = __bfloat162float(__low2bfloat16(x));
            float l0 = t0[0] - hh;
            hh = __bfloat162float(__high2bfloat16(x));
            pal[0] = pack_bf2(l0, t0[1] - hh);

            x = __floats2bfloat162_rn(t0[2], t0[3]);
            pah[1] = *reinterpret_cast<uint32_t*>(&x);
            hh = __bfloat162float(__low2bfloat16(x));
            l0 = t0[2] - hh;
            hh = __bfloat162float(__high2bfloat16(x));
            pal[1] = pack_bf2(l0, t0[3] - hh);

            x = __floats2bfloat162_rn(t1[0], t1[1]);
            pah[2] = *reinterpret_cast<uint32_t*>(&x);
            hh = __bfloat162float(__low2bfloat16(x));
            l0 = t1[0] - hh;
            hh = __bfloat162float(__high2bfloat16(x));
            pal[2] = pack_bf2(l0, t1[1] - hh);

            x = __floats2bfloat162_rn(t1[2], t1[3]);
            pah[3] = *reinterpret_cast<uint32_t*>(&x);
            hh = __bfloat162float(__low2bfloat16(x));
            l0 = t1[2] - hh;
            hh = __bfloat162float(__high2bfloat16(x));
            pal[3] = pack_bf2(l0, t1[3] - hh);
        }
        const uint32_t koff = ks * 32;
        uint32_t vh[2][4], vl[2][4];
        #pragma unroll
        for (int p = 0; p < 2; p++) {
            uint32_t off = ((p * 16 + frow) * VLD + fcol) * 2 + koff;
            ldsm_x4(bVh + off, vh[p][0], vh[p][1], vh[p][2], vh[p][3]);
            ldsm_x4(bVl + off, vl[p][0], vl[p][1], vl[p][2], vl[p][3]);
        }
        #pragma unroll
        for (int j = 0; j < 4; j++) {
            int p = j >> 1, q = j & 1;
            mma_bf16(acco[j], pah, vh[p][q], vh[p][q + 2]);
            mma_bf16(acco[j], pah, vl[p][q], vl[p][q + 2]);
            mma_bf16(acco[j], pal, vh[p][q], vh[p][q + 2]);
        }
    }

    // ---- store split bf16 hi/lo for proj GEMM ----
    {
        const int er = lane >> 2;
        const int ec = (lane & 3) * 2;
        const size_t r0 = (size_t)(b * SEQ + wm + er) * CDIM + h * HDIM + ec;
        const size_t r1 = r0 + (size_t)8 * CDIM;
        #pragma unroll
        for (int j = 0; j < 4; j++) {
            float a0 = acco[j][0], a1 = acco[j][1];
            __nv_bfloat162 x0 = __floats2bfloat162_rn(a0, a1);
            float h0 = __bfloat162float(__low2bfloat16(x0));
            float h1 = __bfloat162float(__high2bfloat16(x0));
            *reinterpret_cast<uint32_t*>(oh + r0 + 8 * j) = *reinterpret_cast<uint32_t*>(&x0);
            *reinterpret_cast<uint32_t*>(ol + r0 + 8 * j) = pack_bf2(a0 - h0, a1 - h1);

            float b0 = acco[j][2], b1 = acco[j][3];
            __nv_bfloat162 x1 = __floats2bfloat162_rn(b0, b1);
            h0 = __bfloat162float(__low2bfloat16(x1));
            h1 = __bfloat162float(__high2bfloat16(x1));
            *reinterpret_cast<uint32_t*>(oh + r1 + 8 * j) = *reinterpret_cast<uint32_t*>(&x1);
            *reinterpret_cast<uint32_t*>(ol + r1 + 8 * j) = pack_bf2(b0 - h0, b1 - h1);
        }
    }
}

// ---------------- launch ----------------------------------------------------
extern "C" void kernel_launch(void* const* d_in, const int* in_sizes, int n_in,
                              void* d_out, int out_size)
{
    const float* x           = (const float*)d_in[0];
    const float* mask        = (const float*)d_in[1];
    const float* qkv_w       = (const float*)d_in[2];
    const float* qkv_b       = (const float*)d_in[3];
    const float* proj_w      = (const float*)d_in[4];
    const float* proj_b      = (const float*)d_in[5];
    const float* logit_scale = (const float*)d_in[6];
    float* out = (float*)d_out;

    float *qkv_buf;
    __nv_bfloat16 *xh, *xl, *ah, *al, *wqh, *wql, *wph, *wpl;
    cudaGetSymbolAddress((void**)&qkv_buf, g_qkv);
    cudaGetSymbolAddress((void**)&xh, g_xh);
    cudaGetSymbolAddress((void**)&xl, g_xl);
    cudaGetSymbolAddress((void**)&ah, g_ah);
    cudaGetSymbolAddress((void**)&al, g_al);
    cudaGetSymbolAddress((void**)&wqh, g_wqh);
    cudaGetSymbolAddress((void**)&wql, g_wql);
    cudaGetSymbolAddress((void**)&wph, g_wph);
    cudaGetSymbolAddress((void**)&wpl, g_wpl);

    cudaFuncSetAttribute(gemm_pre,
        cudaFuncAttributeMaxDynamicSharedMemorySize, 2 * STG_BYTES);

    const int M = MTOT;

    // 0) splits
    {
        int n4 = M * CDIM / 4;
        split_kernel<<<(n4 + 255) / 256, 256>>>(
            (const float4*)x, (uint2*)xh, (uint2*)xl, n4);
        int w4 = 3 * CDIM * CDIM / 4;
        split_kernel<<<(w4 + 255) / 256, 256>>>(
            (const float4*)qkv_w, (uint2*)wqh, (uint2*)wql, w4);
        int p4 = CDIM * CDIM / 4;
        split_kernel<<<(p4 + 255) / 256, 256>>>(
            (const float4*)proj_w, (uint2*)wph, (uint2*)wpl, p4);
    }
    // 1) QKV GEMM
    {
        dim3 grid(3 * CDIM / GBN, M / GBM);   // (12, 2048)
        gemm_pre<<<grid, 256, 2 * STG_BYTES>>>(
            xh, xl, wqh, wql, qkv_b, qkv_buf, M, 3 * CDIM, CDIM);
    }
    // 2) fused RoPE + norm + attention
    {
        dim3 grid(NHEAD, B_WIN);
        attn_mma_kernel<<<grid, 128>>>(mask, logit_scale, ah, al);
    }
    // 3) proj GEMM
    {
        dim3 grid(CDIM / GBN, M / GBM);       // (4, 2048)
        gemm_pre<<<grid, 256, 2 * STG_BYTES>>>(
            ah, al, wph, wpl, proj_b, out, M, CDIM, CDIM);
    }
}

// round 13
// speedup vs baseline: 1.0678x; 1.0678x over previous
#include <cuda_runtime.h>
#include <cuda_bf16.h>
#include <cstdint>

// Problem constants
#define B_WIN   4096
#define SEQ     64
#define CDIM    256
#define NHEAD   8
#define HDIM    32
#define NWIN    64
#define MAX_LOGIT 4.6051701859880913680f  // log(100)

// ---------------- scratch (device globals; no runtime allocation) ----------
__device__ float g_qkv[(size_t)B_WIN * SEQ * 3 * CDIM];   // [b*64+n][768]
__device__ float g_attn[(size_t)B_WIN * SEQ * CDIM];      // [b*64+n][256]

// ================= common mma helpers ======================================
__device__ __forceinline__ uint32_t pack_bf2(float a, float b) {
    __nv_bfloat162 t = __floats2bfloat162_rn(a, b);
    return *reinterpret_cast<uint32_t*>(&t);
}

__device__ __forceinline__ void ldsm_x4(uint32_t addr, uint32_t& r0, uint32_t& r1,
                                        uint32_t& r2, uint32_t& r3) {
    asm volatile("ldmatrix.sync.aligned.m8n8.x4.shared.b16 {%0,%1,%2,%3}, [%4];"
                 : "=r"(r0), "=r"(r1), "=r"(r2), "=r"(r3) : "r"(addr));
}

__device__ __forceinline__ void mma_bf16(float* c, const uint32_t* a,
                                         uint32_t b0, uint32_t b1) {
    asm volatile(
        "mma.sync.aligned.m16n8k16.row.col.f32.bf16.bf16.f32 "
        "{%0,%1,%2,%3}, {%4,%5,%6,%7}, {%8,%9}, {%0,%1,%2,%3};"
        : "+f"(c[0]), "+f"(c[1]), "+f"(c[2]), "+f"(c[3])
        : "r"(a[0]), "r"(a[1]), "r"(a[2]), "r"(a[3]), "r"(b0), "r"(b1));
}

// split float4 into hi/lo bf16x4 packed as uint2
__device__ __forceinline__ void split4(float4 v, uint2& hi, uint2& lo) {
    float vv[4] = {v.x, v.y, v.z, v.w};
    float hf[4], lf[4];
    #pragma unroll
    for (int j = 0; j < 4; j++) {
        __nv_bfloat16 h = __float2bfloat16_rn(vv[j]);
        hf[j] = __bfloat162float(h);
        lf[j] = vv[j] - hf[j];
    }
    hi.x = pack_bf2(hf[0], hf[1]); hi.y = pack_bf2(hf[2], hf[3]);
    lo.x = pack_bf2(lf[0], lf[1]); lo.y = pack_bf2(lf[2], lf[3]);
}

// ================= bf16-split tensor-core GEMM =============================
#define GBM 128
#define GBN 64
#define GBK 32
#define LDS 40

__global__ __launch_bounds__(256, 2) void gemm_bf16_split(
    const float* __restrict__ A, const float* __restrict__ Bw,
    const float* __restrict__ bias, float* __restrict__ C,
    int M, int N, int K)
{
    __shared__ __align__(16) __nv_bfloat16 sAh[GBM * LDS];
    __shared__ __align__(16) __nv_bfloat16 sAl[GBM * LDS];
    __shared__ __align__(16) __nv_bfloat16 sBh[GBN * LDS];
    __shared__ __align__(16) __nv_bfloat16 sBl[GBN * LDS];

    const int tid  = threadIdx.x;
    const int lane = tid & 31;
    const int wid  = tid >> 5;
    const int bm   = blockIdx.y * GBM;
    const int bn   = blockIdx.x * GBN;
    const int wm   = (wid & 3) * 32;
    const int wn   = (wid >> 2) * 32;

    const int lr   = lane & 7;
    const int seg  = lane >> 3;
    const int frow = lr + (seg & 1) * 8;
    const int fcol = (seg >> 1) * 8;

    const uint32_t bAh = (uint32_t)__cvta_generic_to_shared(sAh);
    const uint32_t bAl = (uint32_t)__cvta_generic_to_shared(sAl);
    const uint32_t bBh = (uint32_t)__cvta_generic_to_shared(sBh);
    const uint32_t bBl = (uint32_t)__cvta_generic_to_shared(sBl);

    uint32_t aAh[2], aAl[2], aBh[2], aBl[2];
    #pragma unroll
    for (int mt = 0; mt < 2; mt++) {
        uint32_t off = ((wm + mt * 16 + frow) * LDS + fcol) * 2;
        aAh[mt] = bAh + off; aAl[mt] = bAl + off;
    }
    #pragma unroll
    for (int p = 0; p < 2; p++) {
        uint32_t off = ((wn + p * 16 + frow) * LDS + fcol) * 2;
        aBh[p] = bBh + off; aBl[p] = bBl + off;
    }

    float acc[2][4][4];
    #pragma unroll
    for (int mt = 0; mt < 2; mt++)
        #pragma unroll
        for (int nt = 0; nt < 4; nt++)
            #pragma unroll
            for (int j = 0; j < 4; j++) acc[mt][nt][j] = 0.f;

    float4 pa[4], pb[2];
    const int nkb = K / GBK;

    {
        const float* Ap = A + (size_t)bm * K;
        const float* Bp = Bw + (size_t)bn * K;
        #pragma unroll
        for (int i = 0; i < 4; i++) {
            int s = i * 256 + tid;
            pa[i] = *reinterpret_cast<const float4*>(Ap + (size_t)(s >> 3) * K + (s & 7) * 4);
        }
        #pragma unroll
        for (int i = 0; i < 2; i++) {
            int s = i * 256 + tid;
            pb[i] = *reinterpret_cast<const float4*>(Bp + (size_t)(s >> 3) * K + (s & 7) * 4);
        }
    }
    {
        #pragma unroll
        for (int i = 0; i < 4; i++) {
            int s = i * 256 + tid; int r = s >> 3, c = (s & 7) * 4;
            uint2 hi, lo; split4(pa[i], hi, lo);
            *reinterpret_cast<uint2*>(sAh + r * LDS + c) = hi;
            *reinterpret_cast<uint2*>(sAl + r * LDS + c) = lo;
        }
        #pragma unroll
        for (int i = 0; i < 2; i++) {
            int s = i * 256 + tid; int r = s >> 3, c = (s & 7) * 4;
            uint2 hi, lo; split4(pb[i], hi, lo);
            *reinterpret_cast<uint2*>(sBh + r * LDS + c) = hi;
            *reinterpret_cast<uint2*>(sBl + r * LDS + c) = lo;
        }
    }
    __syncthreads();

    for (int kb = 0; kb < nkb; kb++) {
        if (kb + 1 < nkb) {
            const float* Ap = A + (size_t)bm * K + (kb + 1) * GBK;
            const float* Bp = Bw + (size_t)bn * K + (kb + 1) * GBK;
            #pragma unroll
            for (int i = 0; i < 4; i++) {
                int s = i * 256 + tid;
                pa[i] = *reinterpret_cast<const float4*>(Ap + (size_t)(s >> 3) * K + (s & 7) * 4);
            }
            #pragma unroll
            for (int i = 0; i < 2; i++) {
                int s = i * 256 + tid;
                pb[i] = *reinterpret_cast<const float4*>(Bp + (size_t)(s >> 3) * K + (s & 7) * 4);
            }
        }

        #pragma unroll
        for (int ks = 0; ks < 2; ks++) {
            const uint32_t koff = ks * 32;
            uint32_t ah[2][4], al[2][4], bh[2][4], bl[2][4];
            #pragma unroll
            for (int mt = 0; mt < 2; mt++) {
                ldsm_x4(aAh[mt] + koff, ah[mt][0], ah[mt][1], ah[mt][2], ah[mt][3]);
                ldsm_x4(aAl[mt] + koff, al[mt][0], al[mt][1], al[mt][2], al[mt][3]);
            }
            #pragma unroll
            for (int p = 0; p < 2; p++) {
                ldsm_x4(aBh[p] + koff, bh[p][0], bh[p][1], bh[p][2], bh[p][3]);
                ldsm_x4(aBl[p] + koff, bl[p][0], bl[p][1], bl[p][2], bl[p][3]);
            }
            // ---- pass-major ordering: 8 independent accs between reuses ----
            #pragma unroll
            for (int mt = 0; mt < 2; mt++)
                #pragma unroll
                for (int nt = 0; nt < 4; nt++) {
                    int p = nt >> 1, q = nt & 1;
                    mma_bf16(acc[mt][nt], ah[mt], bh[p][q], bh[p][q + 2]); // hh
                }
            #pragma unroll
            for (int mt = 0; mt < 2; mt++)
                #pragma unroll
                for (int nt = 0; nt < 4; nt++) {
                    int p = nt >> 1, q = nt & 1;
                    mma_bf16(acc[mt][nt], ah[mt], bl[p][q], bl[p][q + 2]); // hl
                }
            #pragma unroll
            for (int mt = 0; mt < 2; mt++)
                #pragma unroll
                for (int nt = 0; nt < 4; nt++) {
                    int p = nt >> 1, q = nt & 1;
                    mma_bf16(acc[mt][nt], al[mt], bh[p][q], bh[p][q + 2]); // lh
                }
        }

        if (kb + 1 < nkb) {
            __syncthreads();
            #pragma unroll
            for (int i = 0; i < 4; i++) {
                int s = i * 256 + tid; int r = s >> 3, c = (s & 7) * 4;
                uint2 hi, lo; split4(pa[i], hi, lo);
                *reinterpret_cast<uint2*>(sAh + r * LDS + c) = hi;
                *reinterpret_cast<uint2*>(sAl + r * LDS + c) = lo;
            }
            #pragma unroll
            for (int i = 0; i < 2; i++) {
                int s = i * 256 + tid; int r = s >> 3, c = (s & 7) * 4;
                uint2 hi, lo; split4(pb[i], hi, lo);
                *reinterpret_cast<uint2*>(sBh + r * LDS + c) = hi;
                *reinterpret_cast<uint2*>(sBl + r * LDS + c) = lo;
            }
            __syncthreads();
        }
    }

    const int er = lane >> 2;
    const int ec = (lane & 3) * 2;
    #pragma unroll
    for (int mt = 0; mt < 2; mt++) {
        #pragma unroll
        for (int nt = 0; nt < 4; nt++) {
            int row = bm + wm + mt * 16 + er;
            int col = bn + wn + nt * 8 + ec;
            float b0 = bias[col], b1 = bias[col + 1];
            float2 o0 = make_float2(acc[mt][nt][0] + b0, acc[mt][nt][1] + b1);
            float2 o1 = make_float2(acc[mt][nt][2] + b0, acc[mt][nt][3] + b1);
            *reinterpret_cast<float2*>(C + (size_t)row * N + col) = o0;
            *reinterpret_cast<float2*>(C + (size_t)(row + 8) * N + col) = o1;
        }
    }
}

// ============ fused RoPE + norm + tensor-core attention per (b,h) ==========
#define VLD 72   // V^T row length (64 + 8 pad)

__global__ __launch_bounds__(128) void attn_mma_kernel(
    const float* __restrict__ mask, const float* __restrict__ logit_scale,
    float* __restrict__ out)
{
    const int h = blockIdx.x;
    const int b = blockIdx.y;
    const int w = b & (NWIN - 1);
    const int tid  = threadIdx.x;
    const int lane = tid & 31;
    const int wid  = tid >> 5;

    __shared__ __align__(16) __nv_bfloat16 qh[SEQ * LDS];
    __shared__ __align__(16) __nv_bfloat16 ql[SEQ * LDS];
    __shared__ __align__(16) __nv_bfloat16 kh[SEQ * LDS];
    __shared__ __align__(16) __nv_bfloat16 kl[SEQ * LDS];
    __shared__ __align__(16) __nv_bfloat16 vth[HDIM * VLD];
    __shared__ __align__(16) __nv_bfloat16 vtl[HDIM * VLD];
    __shared__ float msk[SEQ][SEQ + 4];

    const float* base = g_qkv + (size_t)b * SEQ * (3 * CDIM) + h * HDIM;

    // ---- load q or k row, RoPE + normalize, split to bf16 hi/lo ----
    {
        const int s = tid >> 6;
        const int n = tid & 63;
        const float* rp = base + (size_t)n * (3 * CDIM) + s * CDIM;
        float v[32];
        #pragma unroll
        for (int i = 0; i < 8; i++) {
            float4 t = *reinterpret_cast<const float4*>(rp + i * 4);
            v[i*4+0]=t.x; v[i*4+1]=t.y; v[i*4+2]=t.z; v[i*4+3]=t.w;
        }
        float r[32];
        const float tp = (float)n + 0.1f;
        #pragma unroll
        for (int i = 0; i < 16; i++) {
            float inv_freq = exp2f(-(float)i * 0.8304820237218405f);
            float ang = tp * inv_freq;
            float sn = sinf(ang), cs = cosf(ang);
            r[i]      = v[i] * cs - v[i + 16] * sn;
            r[i + 16] = v[i] * sn + v[i + 16] * cs;
        }
        float ss = 0.f;
        #pragma unroll
        for (int i = 0; i < 32; i++) ss += r[i] * r[i];
        float inv = 1.0f / fmaxf(sqrtf(ss), 1e-12f);
        __nv_bfloat16* dh = (s == 0 ? qh : kh) + n * LDS;
        __nv_bfloat16* dl = (s == 0 ? ql : kl) + n * LDS;
        #pragma unroll
        for (int i = 0; i < 32; i += 2) {
            float a0 = r[i] * inv, a1 = r[i + 1] * inv;
            __nv_bfloat162 hi2 = __floats2bfloat162_rn(a0, a1);
            float h0 = __bfloat162float(__low2bfloat16(hi2));
            float h1 = __bfloat162float(__high2bfloat16(hi2));
            *reinterpret_cast<uint32_t*>(dh + i) = *reinterpret_cast<uint32_t*>(&hi2);
            *reinterpret_cast<uint32_t*>(dl + i) = pack_bf2(a0 - h0, a1 - h1);
        }
    }
    // ---- load V transposed, split hi/lo ----
    {
        const int n = tid & 63;
        const int dh0 = (tid >> 6) * 16;
        const float* rp = base + (size_t)n * (3 * CDIM) + 2 * CDIM + dh0;
        #pragma unroll
        for (int i = 0; i < 4; i++) {
            float4 t = *reinterpret_cast<const float4*>(rp + i * 4);
            float vv[4] = {t.x, t.y, t.z, t.w};
            #pragma unroll
            for (int j = 0; j < 4; j++) {
                int d = dh0 + i * 4 + j;
                __nv_bfloat16 hb = __float2bfloat16_rn(vv[j]);
                vth[d * VLD + n] = hb;
                vtl[d * VLD + n] = __float2bfloat16_rn(vv[j] - __bfloat162float(hb));
            }
        }
    }
    // ---- load mask tile ----
    {
        const float* mp = mask + (size_t)w * SEQ * SEQ;
        #pragma unroll
        for (int i = 0; i < 8; i++) {
            int s = i * 128 + tid;
            int r = s >> 4, c4 = (s & 15) * 4;
            *reinterpret_cast<float4*>(&msk[r][c4]) =
                *reinterpret_cast<const float4*>(mp + r * SEQ + c4);
        }
    }
    const float scale = expf(fminf(logit_scale[h], MAX_LOGIT));
    __syncthreads();

    const int lr   = lane & 7;
    const int seg  = lane >> 3;
    const int frow = lr + (seg & 1) * 8;
    const int fcol = (seg >> 1) * 8;
    const int wm   = wid * 16;

    const uint32_t bQh = (uint32_t)__cvta_generic_to_shared(qh);
    const uint32_t bQl = (uint32_t)__cvta_generic_to_shared(ql);
    const uint32_t bKh = (uint32_t)__cvta_generic_to_shared(kh);
    const uint32_t bKl = (uint32_t)__cvta_generic_to_shared(kl);
    const uint32_t bVh = (uint32_t)__cvta_generic_to_shared(vth);
    const uint32_t bVl = (uint32_t)__cvta_generic_to_shared(vtl);

    const uint32_t aQ = ((wm + frow) * LDS + fcol) * 2;

    // ---- S = qn . kn^T (3-pass split, pass-major) ----
    float acc[8][4];
    #pragma unroll
    for (int j = 0; j < 8; j++)
        #pragma unroll
        for (int u = 0; u < 4; u++) acc[j][u] = 0.f;

    #pragma unroll
    for (int ks = 0; ks < 2; ks++) {
        const uint32_t koff = ks * 32;
        uint32_t ah[4], al[4];
        ldsm_x4(bQh + aQ + koff, ah[0], ah[1], ah[2], ah[3]);
        ldsm_x4(bQl + aQ + koff, al[0], al[1], al[2], al[3]);
        uint32_t bhf[4][4], blf[4][4];
        #pragma unroll
        for (int p = 0; p < 4; p++) {
            uint32_t off = ((p * 16 + frow) * LDS + fcol) * 2 + koff;
            ldsm_x4(bKh + off, bhf[p][0], bhf[p][1], bhf[p][2], bhf[p][3]);
            ldsm_x4(bKl + off, blf[p][0], blf[p][1], blf[p][2], blf[p][3]);
        }
        // pass-major: 8 independent tiles between same-acc reuses
        #pragma unroll
        for (int j = 0; j < 8; j++) {
            int p = j >> 1, q = j & 1;
            mma_bf16(acc[j], ah, bhf[p][q], bhf[p][q + 2]);   // hh
        }
        #pragma unroll
        for (int j = 0; j < 8; j++) {
            int p = j >> 1, q = j & 1;
            mma_bf16(acc[j], ah, blf[p][q], blf[p][q + 2]);   // hl
        }
        #pragma unroll
        for (int j = 0; j < 8; j++) {
            int p = j >> 1, q = j & 1;
            mma_bf16(acc[j], al, bhf[p][q], bhf[p][q + 2]);   // lh
        }
    }

    // ---- scale + mask + softmax in registers ----
    {
        const int r0 = wm + (lane >> 2);
        const int c0 = (lane & 3) * 2;
        float m0 = -1e30f, m1 = -1e30f;
        #pragma unroll
        for (int j = 0; j < 8; j++) {
            acc[j][0] = fmaf(acc[j][0], scale, msk[r0][8*j + c0]);
            acc[j][1] = fmaf(acc[j][1], scale, msk[r0][8*j + c0 + 1]);
            acc[j][2] = fmaf(acc[j][2], scale, msk[r0 + 8][8*j + c0]);
            acc[j][3] = fmaf(acc[j][3], scale, msk[r0 + 8][8*j + c0 + 1]);
            m0 = fmaxf(m0, fmaxf(acc[j][0], acc[j][1]));
            m1 = fmaxf(m1, fmaxf(acc[j][2], acc[j][3]));
        }
        m0 = fmaxf(m0, __shfl_xor_sync(0xffffffffu, m0, 1));
        m0 = fmaxf(m0, __shfl_xor_sync(0xffffffffu, m0, 2));
        m1 = fmaxf(m1, __shfl_xor_sync(0xffffffffu, m1, 1));
        m1 = fmaxf(m1, __shfl_xor_sync(0xffffffffu, m1, 2));
        float s0 = 0.f, s1 = 0.f;
        #pragma unroll
        for (int j = 0; j < 8; j++) {
            acc[j][0] = __expf(acc[j][0] - m0);
            acc[j][1] = __expf(acc[j][1] - m0);
            acc[j][2] = __expf(acc[j][2] - m1);
            acc[j][3] = __expf(acc[j][3] - m1);
            s0 += acc[j][0] + acc[j][1];
            s1 += acc[j][2] + acc[j][3];
        }
        s0 += __shfl_xor_sync(0xffffffffu, s0, 1);
        s0 += __shfl_xor_sync(0xffffffffu, s0, 2);
        s1 += __shfl_xor_sync(0xffffffffu, s1, 1);
        s1 += __shfl_xor_sync(0xffffffffu, s1, 2);
        float i0 = 1.0f / s0, i1 = 1.0f / s1;
        #pragma unroll
        for (int j = 0; j < 8; j++) {
            acc[j][0] *= i0; acc[j][1] *= i0;
            acc[j][2] *= i1; acc[j][3] *= i1;
        }
    }

    // ---- out = P . V (pass-major across 4 tiles x 4 k-steps) ----
    float acco[4][4];
    #pragma unroll
    for (int j = 0; j < 4; j++)
        #pragma unroll
        for (int u = 0; u < 4; u++) acco[j][u] = 0.f;

    #pragma unroll
    for (int ks = 0; ks < 4; ks++) {
        uint32_t pah[4], pal[4];
        {
            const float* t0 = acc[2 * ks];
            const float* t1 = acc[2 * ks + 1];
            float hh;
            __nv_bfloat162 x;
            x = __floats2bfloat162_rn(t0[0], t0[1]);
            pah[0] = *reinterpret_cast<uint32_t*>(&x);
            hh = __bfloat162float(__low2bfloat16(x));
            float l0 = t0[0] - hh;
            hh = __bfloat162float(__high2bfloat16(x));
            pal[0] = pack_bf2(l0, t0[1] - hh);

            x = __floats2bfloat162_rn(t0[2], t0[3]);
            pah[1] = *reinterpret_cast<uint32_t*>(&x);
            hh = __bfloat162float(__low2bfloat16(x));
            l0 = t0[2] - hh;
            hh = __bfloat162float(__high2bfloat16(x));
            pal[1] = pack_bf2(l0, t0[3] - hh);

            x = __floats2bfloat162_rn(t1[0], t1[1]);
            pah[2] = *reinterpret_cast<uint32_t*>(&x);
            hh = __bfloat162float(__low2bfloat16(x));
            l0 = t1[0] - hh;
            hh = __bfloat162float(__high2bfloat16(x));
            pal[2] = pack_bf2(l0, t1[1] - hh);

            x = __floats2bfloat162_rn(t1[2], t1[3]);
            pah[3] = *reinterpret_cast<uint32_t*>(&x);
            hh = __bfloat162float(__low2bfloat16(x));
            l0 = t1[2] - hh;
            hh = __bfloat162float(__high2bfloat16(x));
            pal[3] = pack_bf2(l0, t1[3] - hh);
        }
        const uint32_t koff = ks * 32;
        uint32_t vh[2][4], vl[2][4];
        #pragma unroll
        for (int p = 0; p < 2; p++) {
            uint32_t off = ((p * 16 + frow) * VLD + fcol) * 2 + koff;
            ldsm_x4(bVh + off, vh[p][0], vh[p][1], vh[p][2], vh[p][3]);
            ldsm_x4(bVl + off, vl[p][0], vl[p][1], vl[p][2], vl[p][3]);
        }
        // pass-major: 4 independent tiles between same-acc reuses
        #pragma unroll
        for (int j = 0; j < 4; j++) {
            int p = j >> 1, q = j & 1;
            mma_bf16(acco[j], pah, vh[p][q], vh[p][q + 2]);   // hh
        }
        #pragma unroll
        for (int j = 0; j < 4; j++) {
            int p = j >> 1, q = j & 1;
            mma_bf16(acco[j], pah, vl[p][q], vl[p][q + 2]);   // hl
        }
        #pragma unroll
        for (int j = 0; j < 4; j++) {
            int p = j >> 1, q = j & 1;
            mma_bf16(acco[j], pal, vh[p][q], vh[p][q + 2]);   // lh
        }
    }

    // ---- store out[b*64 + row][h*32 + d] ----
    {
        const int er = lane >> 2;
        const int ec = (lane & 3) * 2;
        float* orow = out + ((size_t)(b * SEQ + wm + er)) * CDIM + h * HDIM + ec;
        #pragma unroll
        for (int j = 0; j < 4; j++) {
            *reinterpret_cast<float2*>(orow + 8 * j) =
                make_float2(acco[j][0], acco[j][1]);
            *reinterpret_cast<float2*>(orow + 8 * CDIM + 8 * j) =
                make_float2(acco[j][2], acco[j][3]);
        }
    }
}

// ---------------- launch ----------------------------------------------------
extern "C" void kernel_launch(void* const* d_in, const int* in_sizes, int n_in,
                              void* d_out, int out_size)
{
    const float* x           = (const float*)d_in[0];
    const float* mask        = (const float*)d_in[1];
    const float* qkv_w       = (const float*)d_in[2];
    const float* qkv_b       = (const float*)d_in[3];
    const float* proj_w      = (const float*)d_in[4];
    const float* proj_b      = (const float*)d_in[5];
    const float* logit_scale = (const float*)d_in[6];
    float* out = (float*)d_out;

    float* qkv_buf;
    float* attn_buf;
    cudaGetSymbolAddress((void**)&qkv_buf, g_qkv);
    cudaGetSymbolAddress((void**)&attn_buf, g_attn);

    const int M = B_WIN * SEQ;          // 262144

    // 1) QKV GEMM (tensor cores, bf16 split)
    {
        dim3 grid(3 * CDIM / GBN, M / GBM);   // (12, 2048)
        gemm_bf16_split<<<grid, 256>>>(x, qkv_w, qkv_b, qkv_buf, M, 3 * CDIM, CDIM);
    }
    // 2) fused RoPE + norm + attention (tensor cores)
    {
        dim3 grid(NHEAD, B_WIN);
        attn_mma_kernel<<<grid, 128>>>(mask, logit_scale, attn_buf);
    }
    // 3) proj GEMM (tensor cores, bf16 split)
    {
        dim3 grid(CDIM / GBN, M / GBM);       // (4, 2048)
        gemm_bf16_split<<<grid, 256>>>(attn_buf, proj_w, proj_b, out, M, CDIM, CDIM);
    }
}